// round 2
// baseline (speedup 1.0000x reference)
#include <cuda_runtime.h>
#include <cuda_bf16.h>
#include <cstdint>

// Problem dims (fixed by the reference): B=8, S=4096, D=1024
static constexpr int B = 8;
static constexpr int S = 4096;
static constexpr int D = 1024;
static constexpr int D4 = D / 4;          // 256 float4 per row
static constexpr int NROWS = B * S;       // 32768

// Scratch (no cudaMalloc allowed): inclusive cumsum of boundary mask per row,
// and the detected dtype mode of the mask buffer.
__device__ int g_cum[NROWS];
__device__ int g_mode;   // 0 = int32 {0,1}, 1 = float32 {0.0,1.0}, 2 = uint8 bytes

// ---------------------------------------------------------------------------
// Kernel 0: detect how the boolean mask was materialized.
// Inspect the first 8192 32-bit words (safe lower bound across candidate
// layouts: uint8 buffer = 8192 words total; int32/float32 = 32768 words).
//   - all words in {0,1}           -> int32
//   - all words in {0,0x3F800000}  -> float32
//   - otherwise                    -> packed uint8 bytes
// Deterministic: pure function of the input buffer.
// ---------------------------------------------------------------------------
__global__ void detect_mask_mode(const unsigned int* __restrict__ w) {
    __shared__ int sNotBin, sNotFloat;
    if (threadIdx.x == 0) { sNotBin = 0; sNotFloat = 0; }
    __syncthreads();
    int nb = 0, nf = 0;
    for (int i = threadIdx.x; i < 8192; i += blockDim.x) {
        unsigned int v = w[i];
        nb |= (v > 1u);
        nf |= (v != 0u && v != 0x3F800000u);
    }
    if (nb) atomicOr(&sNotBin, 1);
    if (nf) atomicOr(&sNotFloat, 1);
    __syncthreads();
    if (threadIdx.x == 0)
        g_mode = sNotBin ? (sNotFloat ? 2 : 1) : 0;
}

// ---------------------------------------------------------------------------
// Kernel 1: per-batch inclusive cumsum of the boundary mask.
// One block per batch row of S=4096 elements; 1024 threads x 4 elems each.
// Warp-shuffle scan + cross-warp scan in shared memory.
// ---------------------------------------------------------------------------
__global__ void cumsum_kernel(const void* __restrict__ mask_raw) {
    const int b    = blockIdx.x;         // batch
    const int t    = threadIdx.x;        // 0..1023
    const int lane = t & 31;
    const int warp = t >> 5;
    const int base = b * S + t * 4;      // 4 consecutive elements per thread

    const int mode = g_mode;
    int v[4];
    if (mode == 0) {
        const int* m = (const int*)mask_raw;
        #pragma unroll
        for (int i = 0; i < 4; i++) v[i] = (m[base + i] != 0);
    } else if (mode == 1) {
        const float* m = (const float*)mask_raw;
        #pragma unroll
        for (int i = 0; i < 4; i++) v[i] = (m[base + i] != 0.0f);
    } else {
        const unsigned char* m = (const unsigned char*)mask_raw;
        #pragma unroll
        for (int i = 0; i < 4; i++) v[i] = (m[base + i] != 0);
    }

    int s = v[0] + v[1] + v[2] + v[3];

    // warp-level inclusive scan of per-thread sums
    int pre = s;
    #pragma unroll
    for (int o = 1; o < 32; o <<= 1) {
        int n = __shfl_up_sync(0xFFFFFFFFu, pre, o);
        if (lane >= o) pre += n;
    }

    __shared__ int warp_sums[32];
    if (lane == 31) warp_sums[warp] = pre;
    __syncthreads();

    if (warp == 0) {
        int ws = warp_sums[lane];
        #pragma unroll
        for (int o = 1; o < 32; o <<= 1) {
            int n = __shfl_up_sync(0xFFFFFFFFu, ws, o);
            if (lane >= o) ws += n;
        }
        warp_sums[lane] = ws;
    }
    __syncthreads();

    int excl = (pre - s) + (warp > 0 ? warp_sums[warp - 1] : 0);

    int run = excl;
    #pragma unroll
    for (int i = 0; i < 4; i++) {
        run += v[i];
        g_cum[base + i] = run;   // inclusive cumsum
    }
}

// ---------------------------------------------------------------------------
// Kernel 2: the gather. y[b,s,:] = cum>0 ? compressed[b, cum-1, :] : 0.
// Two output rows per block (512 threads, float4 each). Adjacent rows very
// often share the same source chunk row (p(boundary)=0.5 -> ~2 rows/chunk),
// so the second row's loads hit L1/L2.
// ---------------------------------------------------------------------------
__global__ void gather_kernel(const float4* __restrict__ comp,
                              float4* __restrict__ out) {
    const int row = (blockIdx.x << 1) | (threadIdx.x >> 8);  // b*S + s
    const int b   = row >> 12;                               // row / S
    const int cum = g_cum[row];
    const int d   = threadIdx.x & 255;                       // 0..255

    float4 val = make_float4(0.f, 0.f, 0.f, 0.f);
    if (cum > 0) {
        const float4* src = comp + ((long)((b << 12) + (cum - 1))) * D4;
        val = __ldg(&src[d]);
    }
    out[(long)row * D4 + d] = val;
}

// ---------------------------------------------------------------------------
extern "C" void kernel_launch(void* const* d_in, const int* in_sizes, int n_in,
                              void* d_out, int out_size) {
    const float* comp = (const float*)d_in[0];   // [B,S,D] float32
    // d_in[1] = boundary_prob — mathematically irrelevant (scan collapses)
    const void*  mask = d_in[2];                 // [B,S] bool (dtype detected)

    detect_mask_mode<<<1, 256>>>((const unsigned int*)mask);
    cumsum_kernel<<<B, 1024>>>(mask);
    gather_kernel<<<NROWS / 2, 512>>>((const float4*)comp, (float4*)d_out);
}

// round 15
// speedup vs baseline: 1.0917x; 1.0917x over previous
#include <cuda_runtime.h>
#include <cuda_bf16.h>
#include <cstdint>

// Problem dims (fixed by the reference): B=8, S=4096, D=1024
static constexpr int B = 8;
static constexpr int S = 4096;
static constexpr int D = 1024;
static constexpr int D4 = D / 4;          // 256 float4 per row
static constexpr int NROWS = B * S;       // 32768

// Scratch (no cudaMalloc allowed): inclusive cumsum of boundary mask per row.
__device__ int g_cum[NROWS];

// ---------------------------------------------------------------------------
// Kernel 1: fused mask-dtype detection + per-batch inclusive cumsum.
//
// Detection (per block, redundant but deterministic — every block computes the
// same answer from the same first 8192 32-bit words, a safe bound for all
// candidate layouts: uint8 buffer = 8192 words total; int32/float32 = 32768):
//   - all words in {0,1}           -> int32
//   - all words in {0,0x3F800000}  -> float32
//   - otherwise                    -> packed uint8 bytes
// Cost: 8192 words / 1024 threads = 8 loads/thread, L2-hot after block 0.
//
// Cumsum: one block per batch row of S=4096; 1024 threads x 4 elems each.
// ---------------------------------------------------------------------------
__global__ void detect_cumsum_kernel(const void* __restrict__ mask_raw) {
    const int b    = blockIdx.x;         // batch
    const int t    = threadIdx.x;        // 0..1023
    const int lane = t & 31;
    const int warp = t >> 5;

    // ---- inline dtype detection ----
    __shared__ int sNotBin, sNotFloat;
    if (t == 0) { sNotBin = 0; sNotFloat = 0; }
    __syncthreads();
    {
        const unsigned int* w = (const unsigned int*)mask_raw;
        int nb = 0, nf = 0;
        #pragma unroll
        for (int i = 0; i < 8; i++) {
            unsigned int v = w[t + i * 1024];
            nb |= (v > 1u);
            nf |= (v != 0u && v != 0x3F800000u);
        }
        if (__any_sync(0xFFFFFFFFu, nb) && lane == 0) atomicOr(&sNotBin, 1);
        if (__any_sync(0xFFFFFFFFu, nf) && lane == 0) atomicOr(&sNotFloat, 1);
    }
    __syncthreads();
    const int mode = sNotBin ? (sNotFloat ? 2 : 1) : 0;

    // ---- load 4 mask elements per thread ----
    const int base = b * S + t * 4;
    int v[4];
    if (mode == 0) {
        const int* m = (const int*)mask_raw;
        #pragma unroll
        for (int i = 0; i < 4; i++) v[i] = (m[base + i] != 0);
    } else if (mode == 1) {
        const float* m = (const float*)mask_raw;
        #pragma unroll
        for (int i = 0; i < 4; i++) v[i] = (m[base + i] != 0.0f);
    } else {
        const unsigned char* m = (const unsigned char*)mask_raw;
        #pragma unroll
        for (int i = 0; i < 4; i++) v[i] = (m[base + i] != 0);
    }

    int s = v[0] + v[1] + v[2] + v[3];

    // warp-level inclusive scan of per-thread sums
    int pre = s;
    #pragma unroll
    for (int o = 1; o < 32; o <<= 1) {
        int n = __shfl_up_sync(0xFFFFFFFFu, pre, o);
        if (lane >= o) pre += n;
    }

    __shared__ int warp_sums[32];
    if (lane == 31) warp_sums[warp] = pre;
    __syncthreads();

    if (warp == 0) {
        int ws = warp_sums[lane];
        #pragma unroll
        for (int o = 1; o < 32; o <<= 1) {
            int n = __shfl_up_sync(0xFFFFFFFFu, ws, o);
            if (lane >= o) ws += n;
        }
        warp_sums[lane] = ws;
    }
    __syncthreads();

    int excl = (pre - s) + (warp > 0 ? warp_sums[warp - 1] : 0);

    int run = excl;
    #pragma unroll
    for (int i = 0; i < 4; i++) {
        run += v[i];
        g_cum[base + i] = run;   // inclusive cumsum
    }
}

// ---------------------------------------------------------------------------
// Kernel 2: the gather. y[b,s,:] = cum>0 ? compressed[b, cum-1, :] : 0.
// Two output rows per block (512 threads, float4 each). Adjacent rows often
// share the same source chunk row (p(boundary)=0.5 -> ~2 rows/chunk), so the
// second row's loads hit L1/L2.
// Output is written with streaming stores (.cs): it is never re-read and is
// exactly L2-sized (128 MB), so evict-first keeps source chunk rows resident
// in L2 for the re-reads.
// ---------------------------------------------------------------------------
__global__ void gather_kernel(const float4* __restrict__ comp,
                              float4* __restrict__ out) {
    const int row = (blockIdx.x << 1) | (threadIdx.x >> 8);  // b*S + s
    const int b   = row >> 12;                               // row / S
    const int cum = g_cum[row];
    const int d   = threadIdx.x & 255;                       // 0..255

    float4 val = make_float4(0.f, 0.f, 0.f, 0.f);
    if (cum > 0) {
        const float4* src = comp + ((long)((b << 12) + (cum - 1))) * D4;
        val = __ldg(&src[d]);
    }
    float4* dst = out + (long)row * D4 + d;
    asm volatile("st.global.cs.v4.f32 [%0], {%1, %2, %3, %4};"
                 :: "l"(dst), "f"(val.x), "f"(val.y), "f"(val.z), "f"(val.w)
                 : "memory");
}

// ---------------------------------------------------------------------------
extern "C" void kernel_launch(void* const* d_in, const int* in_sizes, int n_in,
                              void* d_out, int out_size) {
    const float* comp = (const float*)d_in[0];   // [B,S,D] float32
    // d_in[1] = boundary_prob — mathematically irrelevant (scan collapses)
    const void*  mask = d_in[2];                 // [B,S] bool (dtype detected)

    detect_cumsum_kernel<<<B, 1024>>>(mask);
    gather_kernel<<<NROWS / 2, 512>>>((const float4*)comp, (float4*)d_out);
}